// round 1
// baseline (speedup 1.0000x reference)
#include <cuda_runtime.h>
#include <cuda_bf16.h>

#define N_NODES 50000
#define N_EDGES 800000
#define D_MAX   128

// ---------------- scratch (allocation-free: __device__ globals) ----------------
__device__ int   g_cnt[N_NODES];
__device__ int   g_row_ptr[N_NODES + 1];
__device__ int   g_wr_ptr[N_NODES];
__device__ int   g_csr_src[N_EDGES];
__device__ float g_csr_w[N_EDGES];
__device__ float g_bufA[(size_t)N_NODES * D_MAX];
__device__ float g_bufB[(size_t)N_NODES * D_MAX];

// ---------------- CSR build ----------------
__global__ void k_zero() {
    int i = blockIdx.x * blockDim.x + threadIdx.x;
    if (i < N_NODES) g_cnt[i] = 0;
}

__global__ void k_hist(const int* __restrict__ ei) {
    int i = blockIdx.x * blockDim.x + threadIdx.x;
    if (i < N_EDGES) atomicAdd(&g_cnt[ei[i]], 1);   // ei[0:E] = dst
}

// single-block 1024-thread chunked exclusive scan over g_cnt -> g_row_ptr / g_wr_ptr
__global__ void k_scan() {
    __shared__ int wsum[32];
    __shared__ int carry;
    const int tid = threadIdx.x, lane = tid & 31, wid = tid >> 5;
    if (tid == 0) carry = 0;
    __syncthreads();
    for (int base = 0; base < N_NODES; base += 1024) {
        int i = base + tid;
        int v = (i < N_NODES) ? g_cnt[i] : 0;
        int x = v;
        #pragma unroll
        for (int o = 1; o < 32; o <<= 1) {
            int y = __shfl_up_sync(0xffffffffu, x, o);
            if (lane >= o) x += y;
        }
        if (lane == 31) wsum[wid] = x;
        __syncthreads();
        if (wid == 0) {
            int ws = wsum[lane];
            #pragma unroll
            for (int o = 1; o < 32; o <<= 1) {
                int y = __shfl_up_sync(0xffffffffu, ws, o);
                if (lane >= o) ws += y;
            }
            wsum[lane] = ws;
        }
        __syncthreads();
        int excl = carry + (wid > 0 ? wsum[wid - 1] : 0) + (x - v);
        if (i < N_NODES) { g_row_ptr[i] = excl; g_wr_ptr[i] = excl; }
        int total = wsum[31];
        __syncthreads();
        if (tid == 0) carry += total;
        __syncthreads();
        (void)total;
    }
    if (tid == 0) g_row_ptr[N_NODES] = N_EDGES;
}

__global__ void k_scatter(const int* __restrict__ ei, const float* __restrict__ ew) {
    int i = blockIdx.x * blockDim.x + threadIdx.x;
    if (i < N_EDGES) {
        int d = ei[i];                 // dst
        int s = ei[N_EDGES + i];       // src
        int pos = atomicAdd(&g_wr_ptr[d], 1);
        g_csr_src[pos] = s;
        g_csr_w[pos]   = ew[i];
    }
}

// ---------------- dense GEMM:  Out[N, DOUT] = X[N,128] @ W[128,DOUT]  ----------------
// block = 256 threads, 64-row tile, k chunked by 64.  smem <= 48KB (no attr calls).
template <int DOUT>
__global__ void __launch_bounds__(256) k_gemm(const float* __restrict__ X,
                                              const float* __restrict__ W,
                                              float* __restrict__ Out) {
    constexpr int TM = 64, KB = 64;
    constexpr int CG = DOUT / 4;       // col groups of 4 floats: 32 or 16
    constexpr int RG = 256 / CG;       // row-group stride: 8 or 16
    constexpr int RT = TM / RG;        // rows per thread: 8 or 4
    extern __shared__ float smem[];
    float* Ws = smem;                  // [KB][DOUT]
    float* Xs = smem + KB * DOUT;      // [TM][KB]

    const int tid   = threadIdx.x;
    const int rbase = blockIdx.x * TM;
    const int cg    = tid % CG;
    const int rg    = tid / CG;

    float acc[RT][4];
    #pragma unroll
    for (int i = 0; i < RT; i++)
        #pragma unroll
        for (int j = 0; j < 4; j++) acc[i][j] = 0.0f;

    for (int kb = 0; kb < 128; kb += KB) {
        __syncthreads();
        // load W chunk (rows kb..kb+63, contiguous)
        for (int i = tid; i < KB * DOUT / 4; i += 256)
            ((float4*)Ws)[i] = ((const float4*)(W + kb * DOUT))[i];
        // load X chunk [TM][KB]
        for (int i = tid; i < TM * KB / 4; i += 256) {
            int r = i / (KB / 4);
            int c = i % (KB / 4);
            int gr = rbase + r;
            float4 v = make_float4(0.f, 0.f, 0.f, 0.f);
            if (gr < N_NODES) v = ((const float4*)(X + (size_t)gr * 128 + kb))[c];
            ((float4*)(Xs + r * KB))[c] = v;
        }
        __syncthreads();

        #pragma unroll 4
        for (int k = 0; k < KB; k += 4) {
            float4 wv0 = *(const float4*)(Ws + (k + 0) * DOUT + cg * 4);
            float4 wv1 = *(const float4*)(Ws + (k + 1) * DOUT + cg * 4);
            float4 wv2 = *(const float4*)(Ws + (k + 2) * DOUT + cg * 4);
            float4 wv3 = *(const float4*)(Ws + (k + 3) * DOUT + cg * 4);
            #pragma unroll
            for (int i = 0; i < RT; i++) {
                float4 xv = *(const float4*)(Xs + (rg + i * RG) * KB + k);
                acc[i][0] += xv.x * wv0.x; acc[i][1] += xv.x * wv0.y;
                acc[i][2] += xv.x * wv0.z; acc[i][3] += xv.x * wv0.w;
                acc[i][0] += xv.y * wv1.x; acc[i][1] += xv.y * wv1.y;
                acc[i][2] += xv.y * wv1.z; acc[i][3] += xv.y * wv1.w;
                acc[i][0] += xv.z * wv2.x; acc[i][1] += xv.z * wv2.y;
                acc[i][2] += xv.z * wv2.z; acc[i][3] += xv.z * wv2.w;
                acc[i][0] += xv.w * wv3.x; acc[i][1] += xv.w * wv3.y;
                acc[i][2] += xv.w * wv3.z; acc[i][3] += xv.w * wv3.w;
            }
        }
    }

    #pragma unroll
    for (int i = 0; i < RT; i++) {
        int gr = rbase + rg + i * RG;
        if (gr < N_NODES) {
            float4 o = make_float4(acc[i][0], acc[i][1], acc[i][2], acc[i][3]);
            *(float4*)(Out + (size_t)gr * DOUT + cg * 4) = o;
        }
    }
}

// ---------------- SpMM (gather, CSR by dst): H[d] = relu?( sum_e w_e * T[src_e] + b ) ----
// one warp per dst node; DOUT=128 -> float4/lane, DOUT=64 -> float2/lane.
template <int DOUT, bool RELU>
__global__ void __launch_bounds__(256) k_spmm(const float* __restrict__ T,
                                              const float* __restrict__ bias,
                                              float* __restrict__ H) {
    const int warp = blockIdx.x * 8 + (threadIdx.x >> 5);
    const int lane = threadIdx.x & 31;
    if (warp >= N_NODES) return;
    const int start = g_row_ptr[warp];
    const int end   = g_row_ptr[warp + 1];

    if (DOUT == 128) {
        float4 acc = make_float4(0.f, 0.f, 0.f, 0.f);
        for (int eb = start; eb < end; eb += 32) {
            int e = eb + lane;
            int s = 0; float w = 0.f;
            if (e < end) { s = g_csr_src[e]; w = g_csr_w[e]; }
            int m = min(32, end - eb);
            #pragma unroll 4
            for (int j = 0; j < m; j++) {
                int   sj = __shfl_sync(0xffffffffu, s, j);
                float wj = __shfl_sync(0xffffffffu, w, j);
                float4 v = *(const float4*)(T + (size_t)sj * 128 + lane * 4);
                acc.x += wj * v.x; acc.y += wj * v.y;
                acc.z += wj * v.z; acc.w += wj * v.w;
            }
        }
        float4 b = ((const float4*)bias)[lane];
        acc.x += b.x; acc.y += b.y; acc.z += b.z; acc.w += b.w;
        if (RELU) {
            acc.x = fmaxf(acc.x, 0.f); acc.y = fmaxf(acc.y, 0.f);
            acc.z = fmaxf(acc.z, 0.f); acc.w = fmaxf(acc.w, 0.f);
        }
        *(float4*)(H + (size_t)warp * 128 + lane * 4) = acc;
    } else {  // DOUT == 64
        float2 acc = make_float2(0.f, 0.f);
        for (int eb = start; eb < end; eb += 32) {
            int e = eb + lane;
            int s = 0; float w = 0.f;
            if (e < end) { s = g_csr_src[e]; w = g_csr_w[e]; }
            int m = min(32, end - eb);
            #pragma unroll 4
            for (int j = 0; j < m; j++) {
                int   sj = __shfl_sync(0xffffffffu, s, j);
                float wj = __shfl_sync(0xffffffffu, w, j);
                float2 v = *(const float2*)(T + (size_t)sj * 64 + lane * 2);
                acc.x += wj * v.x; acc.y += wj * v.y;
            }
        }
        float2 b = ((const float2*)bias)[lane];
        acc.x += b.x; acc.y += b.y;
        if (RELU) { acc.x = fmaxf(acc.x, 0.f); acc.y = fmaxf(acc.y, 0.f); }
        *(float2*)(H + (size_t)warp * 64 + lane * 2) = acc;
    }
}

// ---------------- launch ----------------
extern "C" void kernel_launch(void* const* d_in, const int* in_sizes, int n_in,
                              void* d_out, int out_size) {
    const float* x  = (const float*)d_in[0];
    const int*   ei = (const int*)  d_in[1];   // [2, E]: row0 = dst, row1 = src
    const float* ew = (const float*)d_in[2];
    const float* W1 = (const float*)d_in[3];
    const float* b1 = (const float*)d_in[4];
    const float* W2 = (const float*)d_in[5];
    const float* b2 = (const float*)d_in[6];
    const float* W3 = (const float*)d_in[7];
    const float* b3 = (const float*)d_in[8];
    float* out = (float*)d_out;

    void *pA = nullptr, *pB = nullptr;
    cudaGetSymbolAddress(&pA, g_bufA);
    cudaGetSymbolAddress(&pB, g_bufB);
    float* bufA = (float*)pA;
    float* bufB = (float*)pB;

    // CSR build (recomputed every replay; deterministic work)
    k_zero<<<(N_NODES + 255) / 256, 256>>>();
    k_hist<<<(N_EDGES + 255) / 256, 256>>>(ei);
    k_scan<<<1, 1024>>>();
    k_scatter<<<(N_EDGES + 255) / 256, 256>>>(ei, ew);

    const int gemm_blocks = (N_NODES + 63) / 64;
    const int smem128 = (64 * 128 + 64 * 64) * 4;   // 48 KB
    const int smem64  = (64 * 64  + 64 * 64) * 4;   // 32 KB
    const int spmm_blocks = (N_NODES + 7) / 8;

    // layer 1: H1 = relu(A @ (X @ W1) + b1)
    k_gemm<128><<<gemm_blocks, 256, smem128>>>(x, W1, bufA);
    k_spmm<128, true><<<spmm_blocks, 256>>>(bufA, b1, bufB);
    // layer 2
    k_gemm<128><<<gemm_blocks, 256, smem128>>>(bufB, W2, bufA);
    k_spmm<128, true><<<spmm_blocks, 256>>>(bufA, b2, bufB);
    // layer 3 (width 64, no relu), write straight to d_out
    k_gemm<64><<<gemm_blocks, 256, smem64>>>(bufB, W3, bufA);
    k_spmm<64, false><<<spmm_blocks, 256>>>(bufA, b3, out);
}

// round 2
// speedup vs baseline: 1.0065x; 1.0065x over previous
#include <cuda_runtime.h>
#include <cuda_bf16.h>

#define N_NODES 50000
#define N_EDGES 800000
#define D_MAX   128
#define NB_SCAN ((N_NODES + 1023) / 1024)   // 49

// ---------------- scratch (allocation-free: __device__ globals) ----------------
__device__ int   g_cnt[N_NODES];            // zero-initialized; invariant: zero at entry
__device__ int   g_row_ptr[N_NODES + 1];
__device__ int   g_wr_ptr[N_NODES];
__device__ int   g_bsum[64];
__device__ int   g_boff[64];
__device__ int2  g_csr[N_EDGES];            // {src, bits(w)}
__device__ float g_bufA[(size_t)N_NODES * D_MAX];
__device__ float g_bufB[(size_t)N_NODES * D_MAX];

// ---------------- CSR build ----------------
__global__ void k_hist(const int* __restrict__ ei) {
    int i4 = blockIdx.x * blockDim.x + threadIdx.x;
    if (i4 * 4 < N_EDGES) {
        int4 d = ((const int4*)ei)[i4];
        atomicAdd(&g_cnt[d.x], 1);
        atomicAdd(&g_cnt[d.y], 1);
        atomicAdd(&g_cnt[d.z], 1);
        atomicAdd(&g_cnt[d.w], 1);
    }
}

// block-local exclusive scan, write partials + block totals
__global__ void k_scan1() {
    __shared__ int wsum[32];
    const int tid = threadIdx.x, lane = tid & 31, wid = tid >> 5;
    int i = blockIdx.x * 1024 + tid;
    int v = (i < N_NODES) ? g_cnt[i] : 0;
    int x = v;
    #pragma unroll
    for (int o = 1; o < 32; o <<= 1) {
        int y = __shfl_up_sync(0xffffffffu, x, o);
        if (lane >= o) x += y;
    }
    if (lane == 31) wsum[wid] = x;
    __syncthreads();
    if (wid == 0) {
        int ws = wsum[lane];
        #pragma unroll
        for (int o = 1; o < 32; o <<= 1) {
            int y = __shfl_up_sync(0xffffffffu, ws, o);
            if (lane >= o) ws += y;
        }
        wsum[lane] = ws;
    }
    __syncthreads();
    int excl = (wid > 0 ? wsum[wid - 1] : 0) + x - v;
    if (i < N_NODES) g_row_ptr[i] = excl;
    if (tid == 1023) g_bsum[blockIdx.x] = wsum[31];
}

// scan the 49 block totals (1 block, 64 threads)
__global__ void k_scan2() {
    __shared__ int w0;
    const int tid = threadIdx.x, lane = tid & 31, wid = tid >> 5;
    int v = (tid < NB_SCAN) ? g_bsum[tid] : 0;
    int x = v;
    #pragma unroll
    for (int o = 1; o < 32; o <<= 1) {
        int y = __shfl_up_sync(0xffffffffu, x, o);
        if (lane >= o) x += y;
    }
    if (wid == 0 && lane == 31) w0 = x;
    __syncthreads();
    int excl = x - v + (wid == 1 ? w0 : 0);
    if (tid < NB_SCAN) g_boff[tid] = excl;
}

// add block offsets, duplicate into wr_ptr, re-zero g_cnt for next replay
__global__ void k_scan3() {
    int i = blockIdx.x * 1024 + threadIdx.x;
    int off = g_boff[blockIdx.x];
    if (i < N_NODES) {
        int r = g_row_ptr[i] + off;
        g_row_ptr[i] = r;
        g_wr_ptr[i]  = r;
        g_cnt[i]     = 0;
    }
    if (i == 0) g_row_ptr[N_NODES] = N_EDGES;
}

__global__ void k_scatter(const int* __restrict__ ei, const float* __restrict__ ew) {
    int i4 = blockIdx.x * blockDim.x + threadIdx.x;
    if (i4 * 4 < N_EDGES) {
        int4   d = ((const int4*)ei)[i4];
        int4   s = ((const int4*)(ei + N_EDGES))[i4];
        float4 w = ((const float4*)ew)[i4];
        int p;
        p = atomicAdd(&g_wr_ptr[d.x], 1); g_csr[p] = make_int2(s.x, __float_as_int(w.x));
        p = atomicAdd(&g_wr_ptr[d.y], 1); g_csr[p] = make_int2(s.y, __float_as_int(w.y));
        p = atomicAdd(&g_wr_ptr[d.z], 1); g_csr[p] = make_int2(s.z, __float_as_int(w.z));
        p = atomicAdd(&g_wr_ptr[d.w], 1); g_csr[p] = make_int2(s.w, __float_as_int(w.w));
    }
}

// ---------------- dense GEMM:  Out[N, DOUT] = X[N,128] @ W[128,DOUT] ----------------
// 256 threads, 8x8 register blocking. BM = 128 (DOUT=128) or 256 (DOUT=64).
template <int DOUT>
__global__ void __launch_bounds__(256) k_gemm(const float* __restrict__ X,
                                              const float* __restrict__ W,
                                              float* __restrict__ Out) {
    constexpr int CT  = DOUT / 8;      // col-thread count: 16 or 8
    constexpr int RTH = 256 / CT;      // row-thread count: 16 or 32
    constexpr int BM  = RTH * 8;       // 128 or 256
    constexpr int BK  = 32;

    __shared__ float Xs[BM][BK + 1];   // padded: conflict-free scalar access
    __shared__ float Ws[BK][DOUT];

    const int tid = threadIdx.x;
    const int tc  = tid % CT;
    const int tr  = tid / CT;
    const int rbase = blockIdx.x * BM;

    float acc[8][8];
    #pragma unroll
    for (int i = 0; i < 8; i++)
        #pragma unroll
        for (int j = 0; j < 8; j++) acc[i][j] = 0.0f;

    for (int kb = 0; kb < 128; kb += BK) {
        // W chunk: rows kb..kb+BK-1, contiguous float4 copy
        for (int t = tid; t < BK * DOUT / 4; t += 256)
            ((float4*)&Ws[0][0])[t] = ((const float4*)(W + kb * DOUT))[t];
        // X chunk: BM rows x BK cols, coalesced float4 load, scalar scatter (conflict-free)
        for (int t = tid; t < BM * (BK / 4); t += 256) {
            int r  = t >> 3;
            int c4 = t & 7;
            int gr = rbase + r;
            float4 v = make_float4(0.f, 0.f, 0.f, 0.f);
            if (gr < N_NODES) v = *(const float4*)(X + (size_t)gr * 128 + kb + c4 * 4);
            Xs[r][c4 * 4 + 0] = v.x;
            Xs[r][c4 * 4 + 1] = v.y;
            Xs[r][c4 * 4 + 2] = v.z;
            Xs[r][c4 * 4 + 3] = v.w;
        }
        __syncthreads();

        #pragma unroll
        for (int k = 0; k < BK; k++) {
            float xv[8], wv[8];
            #pragma unroll
            for (int i = 0; i < 8; i++) xv[i] = Xs[tr * 8 + i][k];
            *(float4*)&wv[0] = *(const float4*)&Ws[k][tc * 8];
            *(float4*)&wv[4] = *(const float4*)&Ws[k][tc * 8 + 4];
            #pragma unroll
            for (int i = 0; i < 8; i++)
                #pragma unroll
                for (int j = 0; j < 8; j++)
                    acc[i][j] += xv[i] * wv[j];
        }
        __syncthreads();
    }

    #pragma unroll
    for (int i = 0; i < 8; i++) {
        int gr = rbase + tr * 8 + i;
        if (gr < N_NODES) {
            *(float4*)(Out + (size_t)gr * DOUT + tc * 8) =
                make_float4(acc[i][0], acc[i][1], acc[i][2], acc[i][3]);
            *(float4*)(Out + (size_t)gr * DOUT + tc * 8 + 4) =
                make_float4(acc[i][4], acc[i][5], acc[i][6], acc[i][7]);
        }
    }
}

// ---------------- SpMM (gather, CSR by dst): H[d] = relu?( sum w_e * T[src_e] + b ) ----
template <int DOUT, bool RELU>
__global__ void __launch_bounds__(256) k_spmm(const float* __restrict__ T,
                                              const float* __restrict__ bias,
                                              float* __restrict__ H) {
    const int warp = blockIdx.x * 8 + (threadIdx.x >> 5);
    const int lane = threadIdx.x & 31;
    if (warp >= N_NODES) return;
    const int start = g_row_ptr[warp];
    const int end   = g_row_ptr[warp + 1];

    if (DOUT == 128) {
        float4 acc = make_float4(0.f, 0.f, 0.f, 0.f);
        for (int eb = start; eb < end; eb += 32) {
            int e = eb + lane;
            int2 ed = make_int2(0, 0);
            if (e < end) ed = g_csr[e];
            int m = min(32, end - eb);
            #pragma unroll 4
            for (int j = 0; j < m; j++) {
                int   sj = __shfl_sync(0xffffffffu, ed.x, j);
                float wj = __int_as_float(__shfl_sync(0xffffffffu, ed.y, j));
                float4 v = *(const float4*)(T + (size_t)sj * 128 + lane * 4);
                acc.x += wj * v.x; acc.y += wj * v.y;
                acc.z += wj * v.z; acc.w += wj * v.w;
            }
        }
        float4 b = ((const float4*)bias)[lane];
        acc.x += b.x; acc.y += b.y; acc.z += b.z; acc.w += b.w;
        if (RELU) {
            acc.x = fmaxf(acc.x, 0.f); acc.y = fmaxf(acc.y, 0.f);
            acc.z = fmaxf(acc.z, 0.f); acc.w = fmaxf(acc.w, 0.f);
        }
        *(float4*)(H + (size_t)warp * 128 + lane * 4) = acc;
    } else {  // DOUT == 64
        float2 acc = make_float2(0.f, 0.f);
        for (int eb = start; eb < end; eb += 32) {
            int e = eb + lane;
            int2 ed = make_int2(0, 0);
            if (e < end) ed = g_csr[e];
            int m = min(32, end - eb);
            #pragma unroll 4
            for (int j = 0; j < m; j++) {
                int   sj = __shfl_sync(0xffffffffu, ed.x, j);
                float wj = __int_as_float(__shfl_sync(0xffffffffu, ed.y, j));
                float2 v = *(const float2*)(T + (size_t)sj * 64 + lane * 2);
                acc.x += wj * v.x; acc.y += wj * v.y;
            }
        }
        float2 b = ((const float2*)bias)[lane];
        acc.x += b.x; acc.y += b.y;
        if (RELU) { acc.x = fmaxf(acc.x, 0.f); acc.y = fmaxf(acc.y, 0.f); }
        *(float2*)(H + (size_t)warp * 64 + lane * 2) = acc;
    }
}

// ---------------- launch ----------------
extern "C" void kernel_launch(void* const* d_in, const int* in_sizes, int n_in,
                              void* d_out, int out_size) {
    const float* x  = (const float*)d_in[0];
    const int*   ei = (const int*)  d_in[1];   // [2, E]: row0 = dst, row1 = src
    const float* ew = (const float*)d_in[2];
    const float* W1 = (const float*)d_in[3];
    const float* b1 = (const float*)d_in[4];
    const float* W2 = (const float*)d_in[5];
    const float* b2 = (const float*)d_in[6];
    const float* W3 = (const float*)d_in[7];
    const float* b3 = (const float*)d_in[8];
    float* out = (float*)d_out;

    void *pA = nullptr, *pB = nullptr;
    cudaGetSymbolAddress(&pA, g_bufA);
    cudaGetSymbolAddress(&pB, g_bufB);
    float* bufA = (float*)pA;
    float* bufB = (float*)pB;

    // CSR build (g_cnt is zero on entry; k_scan3 re-zeroes it for the next replay)
    const int e4_blocks = (N_EDGES / 4 + 255) / 256;
    k_hist<<<e4_blocks, 256>>>(ei);
    k_scan1<<<NB_SCAN, 1024>>>();
    k_scan2<<<1, 64>>>();
    k_scan3<<<NB_SCAN, 1024>>>();
    k_scatter<<<e4_blocks, 256>>>(ei, ew);

    const int gemm_blocks128 = (N_NODES + 127) / 128;
    const int gemm_blocks64  = (N_NODES + 255) / 256;
    const int spmm_blocks    = (N_NODES + 7) / 8;

    // layer 1: H1 = relu(A @ (X @ W1) + b1)
    k_gemm<128><<<gemm_blocks128, 256>>>(x, W1, bufA);
    k_spmm<128, true><<<spmm_blocks, 256>>>(bufA, b1, bufB);
    // layer 2
    k_gemm<128><<<gemm_blocks128, 256>>>(bufB, W2, bufA);
    k_spmm<128, true><<<spmm_blocks, 256>>>(bufA, b2, bufB);
    // layer 3 (width 64, no relu) -> d_out
    k_gemm<64><<<gemm_blocks64, 256>>>(bufB, W3, bufA);
    k_spmm<64, false><<<spmm_blocks, 256>>>(bufA, b3, out);
}

// round 4
// speedup vs baseline: 1.5060x; 1.4962x over previous
#include <cuda_runtime.h>
#include <cuda_bf16.h>
#include <cstdint>

#define N_NODES 50000
#define N_EDGES 800000
#define D_MAX   128
#define NB_SCAN ((N_NODES + 1023) / 1024)   // 49

// ---------------- scratch (allocation-free: __device__ globals) ----------------
__device__ int   g_cnt[N_NODES];            // zero-initialized; invariant: zero at entry
__device__ int   g_row_ptr[N_NODES + 1];
__device__ int   g_wr_ptr[N_NODES];
__device__ int   g_bsum[64];
__device__ int   g_boff[64];
__device__ int2  g_csr[N_EDGES];            // {src, bits(w)}
__device__ float g_bufA[(size_t)N_NODES * D_MAX];
__device__ float g_bufB[(size_t)N_NODES * D_MAX];
__device__ __nv_bfloat16 g_whi[128 * 128];  // W^T hi, [N,K] row-major
__device__ __nv_bfloat16 g_wlo[128 * 128];  // W^T lo

// ================= helpers =================
__device__ __forceinline__ uint32_t smem_u32(const void* p) {
    uint32_t a;
    asm("{ .reg .u64 t; cvta.to.shared.u64 t, %1; cvt.u32.u64 %0, t; }" : "=r"(a) : "l"(p));
    return a;
}

// pack float2 -> bf16x2 (hi part) and residual bf16x2 (lo part)
__device__ __forceinline__ void bf16_split(float2 f, uint32_t& h, uint32_t& l) {
    asm("cvt.rn.bf16x2.f32 %0, %1, %2;" : "=r"(h) : "f"(f.y), "f"(f.x));  // hi<-f.y, lo<-f.x
    float h0 = __uint_as_float((h & 0x0000FFFFu) << 16);
    float h1 = __uint_as_float(h & 0xFFFF0000u);
    float l0 = f.x - h0;
    float l1 = f.y - h1;
    asm("cvt.rn.bf16x2.f32 %0, %1, %2;" : "=r"(l) : "f"(l1), "f"(l0));
}

#define LDSM4(d0, d1, d2, d3, addr)                                                \
    asm volatile("ldmatrix.sync.aligned.m8n8.x4.shared.b16 {%0,%1,%2,%3}, [%4];"   \
                 : "=r"(d0), "=r"(d1), "=r"(d2), "=r"(d3) : "r"(addr))

#define MMA16816(c, a, b0_, b1_)                                                   \
    asm volatile("mma.sync.aligned.m16n8k16.row.col.f32.bf16.bf16.f32 "            \
                 "{%0,%1,%2,%3}, {%4,%5,%6,%7}, {%8,%9}, {%0,%1,%2,%3};"           \
                 : "+f"((c)[0]), "+f"((c)[1]), "+f"((c)[2]), "+f"((c)[3])          \
                 : "r"((a)[0]), "r"((a)[1]), "r"((a)[2]), "r"((a)[3]),             \
                   "r"(b0_), "r"(b1_))

// ---------------- CSR build ----------------
__global__ void k_hist(const int* __restrict__ ei) {
    int i4 = blockIdx.x * blockDim.x + threadIdx.x;
    if (i4 * 4 < N_EDGES) {
        int4 d = ((const int4*)ei)[i4];
        atomicAdd(&g_cnt[d.x], 1);
        atomicAdd(&g_cnt[d.y], 1);
        atomicAdd(&g_cnt[d.z], 1);
        atomicAdd(&g_cnt[d.w], 1);
    }
}

__global__ void k_scan1() {
    __shared__ int wsum[32];
    const int tid = threadIdx.x, lane = tid & 31, wid = tid >> 5;
    int i = blockIdx.x * 1024 + tid;
    int v = (i < N_NODES) ? g_cnt[i] : 0;
    int x = v;
    #pragma unroll
    for (int o = 1; o < 32; o <<= 1) {
        int y = __shfl_up_sync(0xffffffffu, x, o);
        if (lane >= o) x += y;
    }
    if (lane == 31) wsum[wid] = x;
    __syncthreads();
    if (wid == 0) {
        int ws = wsum[lane];
        #pragma unroll
        for (int o = 1; o < 32; o <<= 1) {
            int y = __shfl_up_sync(0xffffffffu, ws, o);
            if (lane >= o) ws += y;
        }
        wsum[lane] = ws;
    }
    __syncthreads();
    int excl = (wid > 0 ? wsum[wid - 1] : 0) + x - v;
    if (i < N_NODES) g_row_ptr[i] = excl;
    if (tid == 1023) g_bsum[blockIdx.x] = wsum[31];
}

__global__ void k_scan2() {
    __shared__ int w0;
    const int tid = threadIdx.x, lane = tid & 31, wid = tid >> 5;
    int v = (tid < NB_SCAN) ? g_bsum[tid] : 0;
    int x = v;
    #pragma unroll
    for (int o = 1; o < 32; o <<= 1) {
        int y = __shfl_up_sync(0xffffffffu, x, o);
        if (lane >= o) x += y;
    }
    if (wid == 0 && lane == 31) w0 = x;
    __syncthreads();
    int excl = x - v + (wid == 1 ? w0 : 0);
    if (tid < NB_SCAN) g_boff[tid] = excl;
}

__global__ void k_scan3() {
    int i = blockIdx.x * 1024 + threadIdx.x;
    int off = g_boff[blockIdx.x];
    if (i < N_NODES) {
        int r = g_row_ptr[i] + off;
        g_row_ptr[i] = r;
        g_wr_ptr[i]  = r;
        g_cnt[i]     = 0;
    }
    if (i == 0) g_row_ptr[N_NODES] = N_EDGES;
}

__global__ void k_scatter(const int* __restrict__ ei, const float* __restrict__ ew) {
    int i4 = blockIdx.x * blockDim.x + threadIdx.x;
    if (i4 * 4 < N_EDGES) {
        int4   d = ((const int4*)ei)[i4];
        int4   s = ((const int4*)(ei + N_EDGES))[i4];
        float4 w = ((const float4*)ew)[i4];
        int p;
        p = atomicAdd(&g_wr_ptr[d.x], 1); g_csr[p] = make_int2(s.x, __float_as_int(w.x));
        p = atomicAdd(&g_wr_ptr[d.y], 1); g_csr[p] = make_int2(s.y, __float_as_int(w.y));
        p = atomicAdd(&g_wr_ptr[d.z], 1); g_csr[p] = make_int2(s.z, __float_as_int(w.z));
        p = atomicAdd(&g_wr_ptr[d.w], 1); g_csr[p] = make_int2(s.w, __float_as_int(w.w));
    }
}

// ---------------- W prep: W[K=128, DOUT] fp32 -> W^T hi/lo bf16 [DOUT, 128] ----------------
__global__ void k_wprep(const float* __restrict__ W, int dout,
                        __nv_bfloat16* __restrict__ whi, __nv_bfloat16* __restrict__ wlo) {
    int idx = blockIdx.x * blockDim.x + threadIdx.x;
    if (idx < 128 * dout) {
        int k = idx / dout, n = idx % dout;
        float f = W[idx];
        __nv_bfloat16 h = __float2bfloat16_rn(f);
        __nv_bfloat16 l = __float2bfloat16_rn(f - __bfloat162float(h));
        whi[n * 128 + k] = h;
        wlo[n * 128 + k] = l;
    }
}

// ---------------- tensor-core GEMM via legacy mma.sync (sm_80+ path) --------------------
// Out[N_NODES, DOUT] = X[:,128] @ W[128, DOUT], bf16x3 split, fp32 accumulate.
// CTA = 128-row tile, 8 warps x 16 rows. A direct from global into fragments; B in smem.
template <int DOUT>
__global__ void __launch_bounds__(256) k_gemm_mma(const float* __restrict__ X,
                                                  const __nv_bfloat16* __restrict__ whi,
                                                  const __nv_bfloat16* __restrict__ wlo,
                                                  float* __restrict__ Out) {
    constexpr int NT2    = DOUT / 16;     // 8 or 4 (pairs of n-tiles)
    constexpr int STRIDE = 136;           // bf16 elems per smem row (pad 8 -> conflict-free)

    extern __shared__ __nv_bfloat16 bs[];
    __nv_bfloat16* Bh = bs;
    __nv_bfloat16* Bl = bs + DOUT * STRIDE;

    const int tid  = threadIdx.x;
    const int lane = tid & 31;
    const int wid  = tid >> 5;

    // stage W^T hi/lo into smem ([DOUT][128] -> rows with stride 136)
    for (int t = tid; t < DOUT * 16; t += 256) {
        int n = t >> 4, c = t & 15;
        ((uint4*)(Bh + n * STRIDE))[c] = ((const uint4*)(whi + n * 128))[c];
        ((uint4*)(Bl + n * STRIDE))[c] = ((const uint4*)(wlo + n * 128))[c];
    }
    __syncthreads();

    const uint32_t bh_base = smem_u32(Bh);
    const uint32_t bl_base = smem_u32(Bl);

    const int r0 = blockIdx.x * 128 + wid * 16 + (lane >> 2);
    const int r1 = r0 + 8;
    const bool v0 = r0 < N_NODES, v1 = r1 < N_NODES;
    const int kc = (lane & 3) * 2;
    const float* p0 = X + (size_t)r0 * 128 + kc;
    const float* p1 = X + (size_t)r1 * 128 + kc;

    // ldmatrix per-lane row/koff within a 16-n pair of tiles
    const uint32_t lm_row  = (lane & 7) + ((lane >> 4) << 3);   // n offset 0..15
    const uint32_t lm_koff = ((lane >> 3) & 1) * 8;             // k sub-offset 0/8

    float acc[2 * NT2][4];
    #pragma unroll
    for (int i = 0; i < 2 * NT2; i++)
        #pragma unroll
        for (int j = 0; j < 4; j++) acc[i][j] = 0.0f;

    #pragma unroll
    for (int ks = 0; ks < 8; ks++) {
        const int k0 = ks * 16;
        float2 z = make_float2(0.f, 0.f);
        float2 x00 = v0 ? *(const float2*)(p0 + k0)     : z;
        float2 x01 = v0 ? *(const float2*)(p0 + k0 + 8) : z;
        float2 x10 = v1 ? *(const float2*)(p1 + k0)     : z;
        float2 x11 = v1 ? *(const float2*)(p1 + k0 + 8) : z;
        uint32_t ah[4], al[4];
        bf16_split(x00, ah[0], al[0]);
        bf16_split(x10, ah[1], al[1]);
        bf16_split(x01, ah[2], al[2]);
        bf16_split(x11, ah[3], al[3]);

        #pragma unroll
        for (int nt = 0; nt < NT2; nt++) {
            uint32_t off = ((nt * 16 + lm_row) * STRIDE + (uint32_t)k0 + lm_koff) * 2;
            uint32_t h0, h1, h2, h3, l0, l1, l2, l3;
            LDSM4(h0, h1, h2, h3, bh_base + off);
            LDSM4(l0, l1, l2, l3, bl_base + off);
            MMA16816(acc[2 * nt],     ah, h0, h1);
            MMA16816(acc[2 * nt],     ah, l0, l1);
            MMA16816(acc[2 * nt],     al, h0, h1);
            MMA16816(acc[2 * nt + 1], ah, h2, h3);
            MMA16816(acc[2 * nt + 1], ah, l2, l3);
            MMA16816(acc[2 * nt + 1], al, h2, h3);
        }
    }

    // epilogue: c0,c1 -> (r0, n..n+1); c2,c3 -> (r1, n..n+1)
    #pragma unroll
    for (int nt = 0; nt < NT2; nt++) {
        int n0 = nt * 16 + kc;
        if (v0) {
            *(float2*)(Out + (size_t)r0 * DOUT + n0)     = make_float2(acc[2 * nt][0],     acc[2 * nt][1]);
            *(float2*)(Out + (size_t)r0 * DOUT + n0 + 8) = make_float2(acc[2 * nt + 1][0], acc[2 * nt + 1][1]);
        }
        if (v1) {
            *(float2*)(Out + (size_t)r1 * DOUT + n0)     = make_float2(acc[2 * nt][2],     acc[2 * nt][3]);
            *(float2*)(Out + (size_t)r1 * DOUT + n0 + 8) = make_float2(acc[2 * nt + 1][2], acc[2 * nt + 1][3]);
        }
    }
}

// ---------------- SpMM (gather, CSR by dst): H[d] = relu?( sum w_e * T[src_e] + b ) ----
template <int DOUT, bool RELU>
__global__ void __launch_bounds__(256) k_spmm(const float* __restrict__ T,
                                              const float* __restrict__ bias,
                                              float* __restrict__ H) {
    const int warp = blockIdx.x * 8 + (threadIdx.x >> 5);
    const int lane = threadIdx.x & 31;
    if (warp >= N_NODES) return;
    const int start = g_row_ptr[warp];
    const int end   = g_row_ptr[warp + 1];

    if (DOUT == 128) {
        float4 acc = make_float4(0.f, 0.f, 0.f, 0.f);
        for (int eb = start; eb < end; eb += 32) {
            int e = eb + lane;
            int2 ed = make_int2(0, 0);
            if (e < end) ed = g_csr[e];
            int m = min(32, end - eb);
            #pragma unroll 4
            for (int j = 0; j < m; j++) {
                int   sj = __shfl_sync(0xffffffffu, ed.x, j);
                float wj = __int_as_float(__shfl_sync(0xffffffffu, ed.y, j));
                float4 v = *(const float4*)(T + (size_t)sj * 128 + lane * 4);
                acc.x += wj * v.x; acc.y += wj * v.y;
                acc.z += wj * v.z; acc.w += wj * v.w;
            }
        }
        float4 b = ((const float4*)bias)[lane];
        acc.x += b.x; acc.y += b.y; acc.z += b.z; acc.w += b.w;
        if (RELU) {
            acc.x = fmaxf(acc.x, 0.f); acc.y = fmaxf(acc.y, 0.f);
            acc.z = fmaxf(acc.z, 0.f); acc.w = fmaxf(acc.w, 0.f);
        }
        *(float4*)(H + (size_t)warp * 128 + lane * 4) = acc;
    } else {  // DOUT == 64
        float2 acc = make_float2(0.f, 0.f);
        for (int eb = start; eb < end; eb += 32) {
            int e = eb + lane;
            int2 ed = make_int2(0, 0);
            if (e < end) ed = g_csr[e];
            int m = min(32, end - eb);
            #pragma unroll 4
            for (int j = 0; j < m; j++) {
                int   sj = __shfl_sync(0xffffffffu, ed.x, j);
                float wj = __int_as_float(__shfl_sync(0xffffffffu, ed.y, j));
                float2 v = *(const float2*)(T + (size_t)sj * 64 + lane * 2);
                acc.x += wj * v.x; acc.y += wj * v.y;
            }
        }
        float2 b = ((const float2*)bias)[lane];
        acc.x += b.x; acc.y += b.y;
        if (RELU) { acc.x = fmaxf(acc.x, 0.f); acc.y = fmaxf(acc.y, 0.f); }
        *(float2*)(H + (size_t)warp * 64 + lane * 2) = acc;
    }
}

// ---------------- launch ----------------
extern "C" void kernel_launch(void* const* d_in, const int* in_sizes, int n_in,
                              void* d_out, int out_size) {
    const float* x  = (const float*)d_in[0];
    const int*   ei = (const int*)  d_in[1];   // [2, E]: row0 = dst, row1 = src
    const float* ew = (const float*)d_in[2];
    const float* W1 = (const float*)d_in[3];
    const float* b1 = (const float*)d_in[4];
    const float* W2 = (const float*)d_in[5];
    const float* b2 = (const float*)d_in[6];
    const float* W3 = (const float*)d_in[7];
    const float* b3 = (const float*)d_in[8];
    float* out = (float*)d_out;

    void *pA = nullptr, *pB = nullptr, *pWh = nullptr, *pWl = nullptr;
    cudaGetSymbolAddress(&pA, g_bufA);
    cudaGetSymbolAddress(&pB, g_bufB);
    cudaGetSymbolAddress(&pWh, g_whi);
    cudaGetSymbolAddress(&pWl, g_wlo);
    float* bufA = (float*)pA;
    float* bufB = (float*)pB;
    __nv_bfloat16* whi = (__nv_bfloat16*)pWh;
    __nv_bfloat16* wlo = (__nv_bfloat16*)pWl;

    const int smem128 = 2 * 128 * 136 * 2;   // 69,632 B
    const int smem64  = 2 * 64  * 136 * 2;   // 34,816 B
    static bool attr_done = false;
    cudaFuncSetAttribute(k_gemm_mma<128>, cudaFuncAttributeMaxDynamicSharedMemorySize, smem128);
    cudaFuncSetAttribute(k_gemm_mma<64>,  cudaFuncAttributeMaxDynamicSharedMemorySize, smem64);
    (void)attr_done;

    // CSR build (g_cnt zero on entry; k_scan3 re-zeroes for next replay)
    const int e4_blocks = (N_EDGES / 4 + 255) / 256;
    k_hist<<<e4_blocks, 256>>>(ei);
    k_scan1<<<NB_SCAN, 1024>>>();
    k_scan2<<<1, 64>>>();
    k_scan3<<<NB_SCAN, 1024>>>();
    k_scatter<<<e4_blocks, 256>>>(ei, ew);

    const int tiles = (N_NODES + 127) / 128;   // 391
    const int spmm_blocks = (N_NODES + 7) / 8;

    // layer 1: H1 = relu(A @ (X @ W1) + b1)
    k_wprep<<<(128 * 128 + 255) / 256, 256>>>(W1, 128, whi, wlo);
    k_gemm_mma<128><<<tiles, 256, smem128>>>(x, whi, wlo, bufA);
    k_spmm<128, true><<<spmm_blocks, 256>>>(bufA, b1, bufB);
    // layer 2
    k_wprep<<<(128 * 128 + 255) / 256, 256>>>(W2, 128, whi, wlo);
    k_gemm_mma<128><<<tiles, 256, smem128>>>(bufB, whi, wlo, bufA);
    k_spmm<128, true><<<spmm_blocks, 256>>>(bufA, b2, bufB);
    // layer 3 (width 64, no relu) -> d_out
    k_wprep<<<(128 * 64 + 255) / 256, 256>>>(W3, 64, whi, wlo);
    k_gemm_mma<64><<<tiles, 256, smem64>>>(bufB, whi, wlo, bufA);
    k_spmm<64, false><<<spmm_blocks, 256>>>(bufA, b3, out);
}

// round 6
// speedup vs baseline: 1.5554x; 1.0328x over previous
#include <cuda_runtime.h>
#include <cuda_bf16.h>
#include <cstdint>

#define N_NODES 50000
#define N_EDGES 800000
#define D_MAX   128
#define NB_SCAN ((N_NODES + 1023) / 1024)   // 49

// ---------------- scratch (allocation-free: __device__ globals) ----------------
__device__ int   g_cnt[N_NODES];            // zero-initialized; invariant: zero at entry
__device__ int   g_row_ptr[N_NODES + 1];
__device__ int   g_wr_ptr[N_NODES];
__device__ int   g_bsum[64];
__device__ int   g_boff[64];
__device__ int2  g_csr[N_EDGES];            // {src, bits(w)}
__device__ float g_bufA[(size_t)N_NODES * D_MAX];
__device__ float g_bufB[(size_t)N_NODES * D_MAX];
__device__ __nv_bfloat16 g_whi1[128 * 128], g_wlo1[128 * 128];
__device__ __nv_bfloat16 g_whi2[128 * 128], g_wlo2[128 * 128];
__device__ __nv_bfloat16 g_whi3[128 * 64],  g_wlo3[128 * 64];

// ================= helpers =================
__device__ __forceinline__ uint32_t smem_u32(const void* p) {
    uint32_t a;
    asm("{ .reg .u64 t; cvta.to.shared.u64 t, %1; cvt.u32.u64 %0, t; }" : "=r"(a) : "l"(p));
    return a;
}

// pack float2 -> bf16x2 (hi part) and residual bf16x2 (lo part)
__device__ __forceinline__ void bf16_split(float2 f, uint32_t& h, uint32_t& l) {
    asm("cvt.rn.bf16x2.f32 %0, %1, %2;" : "=r"(h) : "f"(f.y), "f"(f.x));  // hi<-f.y, lo<-f.x
    float h0 = __uint_as_float((h & 0x0000FFFFu) << 16);
    float h1 = __uint_as_float(h & 0xFFFF0000u);
    float l0 = f.x - h0;
    float l1 = f.y - h1;
    asm("cvt.rn.bf16x2.f32 %0, %1, %2;" : "=r"(l) : "f"(l1), "f"(l0));
}

#define LDSM4(d0, d1, d2, d3, addr)                                                \
    asm volatile("ldmatrix.sync.aligned.m8n8.x4.shared.b16 {%0,%1,%2,%3}, [%4];"   \
                 : "=r"(d0), "=r"(d1), "=r"(d2), "=r"(d3) : "r"(addr))

#define MMA16816(c, a, b0_, b1_)                                                   \
    asm volatile("mma.sync.aligned.m16n8k16.row.col.f32.bf16.bf16.f32 "            \
                 "{%0,%1,%2,%3}, {%4,%5,%6,%7}, {%8,%9}, {%0,%1,%2,%3};"           \
                 : "+f"((c)[0]), "+f"((c)[1]), "+f"((c)[2]), "+f"((c)[3])          \
                 : "r"((a)[0]), "r"((a)[1]), "r"((a)[2]), "r"((a)[3]),             \
                   "r"(b0_), "r"(b1_))

// ---------------- CSR build ----------------
__global__ void k_hist(const int* __restrict__ ei) {
    int i4 = blockIdx.x * blockDim.x + threadIdx.x;
    if (i4 * 4 < N_EDGES) {
        int4 d = ((const int4*)ei)[i4];
        atomicAdd(&g_cnt[d.x], 1);
        atomicAdd(&g_cnt[d.y], 1);
        atomicAdd(&g_cnt[d.z], 1);
        atomicAdd(&g_cnt[d.w], 1);
    }
}

__global__ void k_scan1() {
    __shared__ int wsum[32];
    const int tid = threadIdx.x, lane = tid & 31, wid = tid >> 5;
    int i = blockIdx.x * 1024 + tid;
    int v = (i < N_NODES) ? g_cnt[i] : 0;
    int x = v;
    #pragma unroll
    for (int o = 1; o < 32; o <<= 1) {
        int y = __shfl_up_sync(0xffffffffu, x, o);
        if (lane >= o) x += y;
    }
    if (lane == 31) wsum[wid] = x;
    __syncthreads();
    if (wid == 0) {
        int ws = wsum[lane];
        #pragma unroll
        for (int o = 1; o < 32; o <<= 1) {
            int y = __shfl_up_sync(0xffffffffu, ws, o);
            if (lane >= o) ws += y;
        }
        wsum[lane] = ws;
    }
    __syncthreads();
    int excl = (wid > 0 ? wsum[wid - 1] : 0) + x - v;
    if (i < N_NODES) g_row_ptr[i] = excl;
    if (tid == 1023) g_bsum[blockIdx.x] = wsum[31];
}

__global__ void k_scan2() {
    __shared__ int w0;
    const int tid = threadIdx.x, lane = tid & 31, wid = tid >> 5;
    int v = (tid < NB_SCAN) ? g_bsum[tid] : 0;
    int x = v;
    #pragma unroll
    for (int o = 1; o < 32; o <<= 1) {
        int y = __shfl_up_sync(0xffffffffu, x, o);
        if (lane >= o) x += y;
    }
    if (wid == 0 && lane == 31) w0 = x;
    __syncthreads();
    int excl = x - v + (wid == 1 ? w0 : 0);
    if (tid < NB_SCAN) g_boff[tid] = excl;
}

__global__ void k_scan3() {
    int i = blockIdx.x * 1024 + threadIdx.x;
    int off = g_boff[blockIdx.x];
    if (i < N_NODES) {
        int r = g_row_ptr[i] + off;
        g_row_ptr[i] = r;
        g_wr_ptr[i]  = r;
        g_cnt[i]     = 0;
    }
    if (i == 0) g_row_ptr[N_NODES] = N_EDGES;
}

__global__ void k_scatter(const int* __restrict__ ei, const float* __restrict__ ew) {
    int i4 = blockIdx.x * blockDim.x + threadIdx.x;
    if (i4 * 4 < N_EDGES) {
        int4   d = ((const int4*)ei)[i4];
        int4   s = ((const int4*)(ei + N_EDGES))[i4];
        float4 w = ((const float4*)ew)[i4];
        int p;
        p = atomicAdd(&g_wr_ptr[d.x], 1); g_csr[p] = make_int2(s.x, __float_as_int(w.x));
        p = atomicAdd(&g_wr_ptr[d.y], 1); g_csr[p] = make_int2(s.y, __float_as_int(w.y));
        p = atomicAdd(&g_wr_ptr[d.z], 1); g_csr[p] = make_int2(s.z, __float_as_int(w.z));
        p = atomicAdd(&g_wr_ptr[d.w], 1); g_csr[p] = make_int2(s.w, __float_as_int(w.w));
    }
}

// ---------------- W prep: W[K=128, DOUT] fp32 -> W^T hi/lo bf16 [DOUT, 128] ----------------
__global__ void k_wprep(const float* __restrict__ W, int dout,
                        __nv_bfloat16* __restrict__ whi, __nv_bfloat16* __restrict__ wlo) {
    int idx = blockIdx.x * blockDim.x + threadIdx.x;
    if (idx < 128 * dout) {
        int k = idx / dout, n = idx % dout;
        float f = W[idx];
        __nv_bfloat16 h = __float2bfloat16_rn(f);
        __nv_bfloat16 l = __float2bfloat16_rn(f - __bfloat162float(h));
        whi[n * 128 + k] = h;
        wlo[n * 128 + k] = l;
    }
}

// ---------------- tensor-core GEMM via mma.sync: Out = X[:,128] @ W[128,DOUT] -----------
// bf16x3 split, fp32 accumulate. CTA = 128-row tile, 8 warps x 16 rows; B in smem.
template <int DOUT>
__global__ void __launch_bounds__(256) k_gemm_mma(const float* __restrict__ X,
                                                  const __nv_bfloat16* __restrict__ whi,
                                                  const __nv_bfloat16* __restrict__ wlo,
                                                  float* __restrict__ Out) {
    constexpr int NT2    = DOUT / 16;     // 8 or 4
    constexpr int STRIDE = 136;           // bf16 elems per smem row (pad 8)

    extern __shared__ __nv_bfloat16 bs[];
    __nv_bfloat16* Bh = bs;
    __nv_bfloat16* Bl = bs + DOUT * STRIDE;

    const int tid  = threadIdx.x;
    const int lane = tid & 31;
    const int wid  = tid >> 5;

    for (int t = tid; t < DOUT * 16; t += 256) {
        int n = t >> 4, c = t & 15;
        ((uint4*)(Bh + n * STRIDE))[c] = ((const uint4*)(whi + n * 128))[c];
        ((uint4*)(Bl + n * STRIDE))[c] = ((const uint4*)(wlo + n * 128))[c];
    }
    __syncthreads();

    const uint32_t bh_base = smem_u32(Bh);
    const uint32_t bl_base = smem_u32(Bl);

    const int r0 = blockIdx.x * 128 + wid * 16 + (lane >> 2);
    const int r1 = r0 + 8;
    const bool v0 = r0 < N_NODES, v1 = r1 < N_NODES;
    const int kc = (lane & 3) * 2;
    const float* p0 = X + (size_t)r0 * 128 + kc;
    const float* p1 = X + (size_t)r1 * 128 + kc;

    const uint32_t lm_row  = (lane & 7) + ((lane >> 4) << 3);
    const uint32_t lm_koff = ((lane >> 3) & 1) * 8;

    float acc[2 * NT2][4];
    #pragma unroll
    for (int i = 0; i < 2 * NT2; i++)
        #pragma unroll
        for (int j = 0; j < 4; j++) acc[i][j] = 0.0f;

    #pragma unroll
    for (int ks = 0; ks < 8; ks++) {
        const int k0 = ks * 16;
        float2 z = make_float2(0.f, 0.f);
        float2 x00 = v0 ? *(const float2*)(p0 + k0)     : z;
        float2 x01 = v0 ? *(const float2*)(p0 + k0 + 8) : z;
        float2 x10 = v1 ? *(const float2*)(p1 + k0)     : z;
        float2 x11 = v1 ? *(const float2*)(p1 + k0 + 8) : z;
        uint32_t ah[4], al[4];
        bf16_split(x00, ah[0], al[0]);
        bf16_split(x10, ah[1], al[1]);
        bf16_split(x01, ah[2], al[2]);
        bf16_split(x11, ah[3], al[3]);

        #pragma unroll
        for (int nt = 0; nt < NT2; nt++) {
            uint32_t off = ((nt * 16 + lm_row) * STRIDE + (uint32_t)k0 + lm_koff) * 2;
            uint32_t h0, h1, h2, h3, l0, l1, l2, l3;
            LDSM4(h0, h1, h2, h3, bh_base + off);
            LDSM4(l0, l1, l2, l3, bl_base + off);
            MMA16816(acc[2 * nt],     ah, h0, h1);
            MMA16816(acc[2 * nt],     ah, l0, l1);
            MMA16816(acc[2 * nt],     al, h0, h1);
            MMA16816(acc[2 * nt + 1], ah, h2, h3);
            MMA16816(acc[2 * nt + 1], ah, l2, l3);
            MMA16816(acc[2 * nt + 1], al, h2, h3);
        }
    }

    #pragma unroll
    for (int nt = 0; nt < NT2; nt++) {
        int n0 = nt * 16 + kc;
        if (v0) {
            *(float2*)(Out + (size_t)r0 * DOUT + n0)     = make_float2(acc[2 * nt][0],     acc[2 * nt][1]);
            *(float2*)(Out + (size_t)r0 * DOUT + n0 + 8) = make_float2(acc[2 * nt + 1][0], acc[2 * nt + 1][1]);
        }
        if (v1) {
            *(float2*)(Out + (size_t)r1 * DOUT + n0)     = make_float2(acc[2 * nt][2],     acc[2 * nt][3]);
            *(float2*)(Out + (size_t)r1 * DOUT + n0 + 8) = make_float2(acc[2 * nt + 1][2], acc[2 * nt + 1][3]);
        }
    }
}

// ---------------- SpMM (gather, CSR by dst): H[d] = relu?( sum w_e * T[src_e] + b ) ----
template <int DOUT, bool RELU>
__global__ void __launch_bounds__(256) k_spmm(const float* __restrict__ T,
                                              const float* __restrict__ bias,
                                              float* __restrict__ H) {
    const int warp = blockIdx.x * 8 + (threadIdx.x >> 5);
    const int lane = threadIdx.x & 31;
    if (warp >= N_NODES) return;
    const int start = g_row_ptr[warp];
    const int end   = g_row_ptr[warp + 1];

    if (DOUT == 128) {
        float4 acc = make_float4(0.f, 0.f, 0.f, 0.f);
        for (int eb = start; eb < end; eb += 32) {
            int e = eb + lane;
            int2 ed = make_int2(0, 0);
            if (e < end) ed = g_csr[e];
            int m = min(32, end - eb);
            #pragma unroll 8
            for (int j = 0; j < m; j++) {
                int   sj = __shfl_sync(0xffffffffu, ed.x, j);
                float wj = __int_as_float(__shfl_sync(0xffffffffu, ed.y, j));
                float4 v = *(const float4*)(T + (size_t)sj * 128 + lane * 4);
                acc.x += wj * v.x; acc.y += wj * v.y;
                acc.z += wj * v.z; acc.w += wj * v.w;
            }
        }
        float4 b = ((const float4*)bias)[lane];
        acc.x += b.x; acc.y += b.y; acc.z += b.z; acc.w += b.w;
        if (RELU) {
            acc.x = fmaxf(acc.x, 0.f); acc.y = fmaxf(acc.y, 0.f);
            acc.z = fmaxf(acc.z, 0.f); acc.w = fmaxf(acc.w, 0.f);
        }
        *(float4*)(H + (size_t)warp * 128 + lane * 4) = acc;
    } else {  // DOUT == 64
        float2 acc = make_float2(0.f, 0.f);
        for (int eb = start; eb < end; eb += 32) {
            int e = eb + lane;
            int2 ed = make_int2(0, 0);
            if (e < end) ed = g_csr[e];
            int m = min(32, end - eb);
            #pragma unroll 8
            for (int j = 0; j < m; j++) {
                int   sj = __shfl_sync(0xffffffffu, ed.x, j);
                float wj = __int_as_float(__shfl_sync(0xffffffffu, ed.y, j));
                float2 v = *(const float2*)(T + (size_t)sj * 64 + lane * 2);
                acc.x += wj * v.x; acc.y += wj * v.y;
            }
        }
        float2 b = ((const float2*)bias)[lane];
        acc.x += b.x; acc.y += b.y;
        if (RELU) { acc.x = fmaxf(acc.x, 0.f); acc.y = fmaxf(acc.y, 0.f); }
        *(float2*)(H + (size_t)warp * 64 + lane * 2) = acc;
    }
}

// ---------------- launch ----------------
extern "C" void kernel_launch(void* const* d_in, const int* in_sizes, int n_in,
                              void* d_out, int out_size) {
    const float* x  = (const float*)d_in[0];
    const int*   ei = (const int*)  d_in[1];   // [2, E]: row0 = dst, row1 = src
    const float* ew = (const float*)d_in[2];
    const float* W1 = (const float*)d_in[3];
    const float* b1 = (const float*)d_in[4];
    const float* W2 = (const float*)d_in[5];
    const float* b2 = (const float*)d_in[6];
    const float* W3 = (const float*)d_in[7];
    const float* b3 = (const float*)d_in[8];
    float* out = (float*)d_out;

    void *pA, *pB, *ph1, *pl1, *ph2, *pl2, *ph3, *pl3;
    cudaGetSymbolAddress(&pA, g_bufA);
    cudaGetSymbolAddress(&pB, g_bufB);
    cudaGetSymbolAddress(&ph1, g_whi1); cudaGetSymbolAddress(&pl1, g_wlo1);
    cudaGetSymbolAddress(&ph2, g_whi2); cudaGetSymbolAddress(&pl2, g_wlo2);
    cudaGetSymbolAddress(&ph3, g_whi3); cudaGetSymbolAddress(&pl3, g_wlo3);
    float* bufA = (float*)pA;
    float* bufB = (float*)pB;
    __nv_bfloat16 *whi1 = (__nv_bfloat16*)ph1, *wlo1 = (__nv_bfloat16*)pl1;
    __nv_bfloat16 *whi2 = (__nv_bfloat16*)ph2, *wlo2 = (__nv_bfloat16*)pl2;
    __nv_bfloat16 *whi3 = (__nv_bfloat16*)ph3, *wlo3 = (__nv_bfloat16*)pl3;

    const int smem128 = 2 * 128 * 136 * 2;   // 69,632 B
    const int smem64  = 2 * 64  * 136 * 2;   // 34,816 B
    cudaFuncSetAttribute(k_gemm_mma<128>, cudaFuncAttributeMaxDynamicSharedMemorySize, smem128);
    cudaFuncSetAttribute(k_gemm_mma<64>,  cudaFuncAttributeMaxDynamicSharedMemorySize, smem64);

    // side stream + fork/join events (leaked deliberately: destroying them while
    // a capture references them is illegal, and kernel_launch runs only ~2 times)
    cudaStream_t s2;
    cudaStreamCreateWithFlags(&s2, cudaStreamNonBlocking);
    cudaEvent_t evFork, evJoin;
    cudaEventCreateWithFlags(&evFork, cudaEventDisableTiming);
    cudaEventCreateWithFlags(&evJoin, cudaEventDisableTiming);

    const int e4_blocks   = (N_EDGES / 4 + 255) / 256;
    const int tiles       = (N_NODES + 127) / 128;   // 391
    const int spmm_blocks = (N_NODES + 7) / 8;

    // ---- fork: branch B on s2 = wpreps + GEMM1 (independent of CSR) ----
    cudaEventRecord(evFork, 0);
    cudaStreamWaitEvent(s2, evFork, 0);
    k_wprep<<<(128 * 128 + 255) / 256, 256, 0, s2>>>(W1, 128, whi1, wlo1);
    k_wprep<<<(128 * 128 + 255) / 256, 256, 0, s2>>>(W2, 128, whi2, wlo2);
    k_wprep<<<(128 * 64 + 255) / 256, 256, 0, s2>>>(W3, 64, whi3, wlo3);
    k_gemm_mma<128><<<tiles, 256, smem128, s2>>>(x, whi1, wlo1, bufA);
    cudaEventRecord(evJoin, s2);

    // ---- branch A on origin stream = CSR build ----
    k_hist<<<e4_blocks, 256>>>(ei);
    k_scan1<<<NB_SCAN, 1024>>>();
    k_scan2<<<1, 64>>>();
    k_scan3<<<NB_SCAN, 1024>>>();
    k_scatter<<<e4_blocks, 256>>>(ei, ew);

    // ---- join, then the serial layer chain ----
    cudaStreamWaitEvent(0, evJoin, 0);
    k_spmm<128, true><<<spmm_blocks, 256>>>(bufA, b1, bufB);
    k_gemm_mma<128><<<tiles, 256, smem128>>>(bufB, whi2, wlo2, bufA);
    k_spmm<128, true><<<spmm_blocks, 256>>>(bufA, b2, bufB);
    k_gemm_mma<64><<<tiles, 256, smem64>>>(bufB, whi3, wlo3, bufA);
    k_spmm<64, false><<<spmm_blocks, 256>>>(bufA, b3, out);
}